// round 7
// baseline (speedup 1.0000x reference)
#include <cuda_runtime.h>
#include <cuda_bf16.h>
#include <cstdint>

// Problem constants
#define NB      16
#define NN      16384
#define NS      256
#define NKS     16
#define C       288
#define PTOT    (NB*NS*NKS)      // 65536 pixels
#define NCHUNK  5                // K padded to 320 = 5 chunks of 64
#define TM      128              // pixels per GEMM CTA
#define NTILES  (PTOT/TM)        // 512
#define J0      4096             // transposed-feature fast-path bound

// FPS distribution
#define FPSG    8                // blocks per batch (16*8=128 <= 148 SMs: co-resident)
#define FPSPTS  (NN/FPSG)        // 2048 points per block
#define FPST    256              // threads per fps block (8 pts/thread in regs)

// byte sizes
#define A_CHUNK_B   (TM*128)             // 16384  (128 rows x 64 bf16)
#define A_TILE_B    (NCHUNK*A_CHUNK_B)   // 81920 per tile per array
#define B_CHUNK_B   (C*128)              // 36864  (288 rows x 64 bf16)
#define W_LAYER_B   (NCHUNK*B_CHUNK_B)   // 184320
#define BH_B        (144*128)            // 18432 per CTA half per chunk

// SMEM stage layout (all 1024-multiples)
#define SA_H  0u
#define SA_L  16384u
#define SB_H  32768u
#define SB_L  51200u
#define STG   69632u
#define DYN_SMEM (2*STG + 1024)          // 140288

// SW128 swizzle (within a 1024-aligned region)
#define SWZ(o) ((o) ^ (((o) >> 3) & 0x70))

// ---------------- scratch ----------------
__device__ __align__(1024) unsigned char d_Xhi[(size_t)NTILES * A_TILE_B];
__device__ __align__(1024) unsigned char d_Xlo[(size_t)NTILES * A_TILE_B];
__device__ __align__(1024) unsigned char d_Yhi[(size_t)NTILES * A_TILE_B];
__device__ __align__(1024) unsigned char d_Ylo[(size_t)NTILES * A_TILE_B];
__device__ __align__(1024) unsigned char d_Whi[3 * W_LAYER_B];
__device__ __align__(1024) unsigned char d_Wlo[3 * W_LAYER_B];
__device__ float d_featT[(size_t)NB * J0 * C];               // (b, n<J0, c) transposed features
__device__ int   d_idx[PTOT];
__device__ float d_newxyz[NB * NS * 3];
__device__ unsigned long long d_fpsKey[NB * NS * FPSG];      // per-(batch,iter,block) packed best
__device__ __align__(16) float4 d_fpsC[NB * NS * FPSG];      // winner candidate coords per slot

// ---------------- PTX helpers (all compute_80-era: safe on compute_103) ----------
__device__ __forceinline__ uint32_t smem_u32(const void* p) {
    uint32_t a;
    asm("{ .reg .u64 t; cvta.to.shared.u64 t, %1; cvt.u32.u64 %0, t; }" : "=r"(a) : "l"(p));
    return a;
}
__device__ __forceinline__ void cp16(uint32_t s, const void* g) {
    asm volatile("cp.async.cg.shared.global [%0], [%1], 16;" :: "r"(s), "l"(g) : "memory");
}
#define CP_COMMIT() asm volatile("cp.async.commit_group;" ::: "memory")
template <int N> __device__ __forceinline__ void cp_wait() {
    asm volatile("cp.async.wait_group %0;" :: "n"(N) : "memory");
}
__device__ __forceinline__ void ldmx4(uint32_t* r, uint32_t a) {
    asm volatile("ldmatrix.sync.aligned.m8n8.x4.shared.b16 {%0,%1,%2,%3}, [%4];"
                 : "=r"(r[0]), "=r"(r[1]), "=r"(r[2]), "=r"(r[3]) : "r"(a));
}
__device__ __forceinline__ void ldmx2(uint32_t* r, uint32_t a) {
    asm volatile("ldmatrix.sync.aligned.m8n8.x2.shared.b16 {%0,%1}, [%2];"
                 : "=r"(r[0]), "=r"(r[1]) : "r"(a));
}
__device__ __forceinline__ void mma16816(float* c, const uint32_t* a, const uint32_t* b) {
    asm volatile("mma.sync.aligned.m16n8k16.row.col.f32.bf16.bf16.f32 "
                 "{%0,%1,%2,%3}, {%4,%5,%6,%7}, {%8,%9}, {%0,%1,%2,%3};"
                 : "+f"(c[0]), "+f"(c[1]), "+f"(c[2]), "+f"(c[3])
                 : "r"(a[0]), "r"(a[1]), "r"(a[2]), "r"(a[3]), "r"(b[0]), "r"(b[1]));
}
__device__ __forceinline__ void st_release_u64(unsigned long long* p, unsigned long long v) {
    asm volatile("st.release.gpu.global.u64 [%0], %1;" :: "l"(p), "l"(v) : "memory");
}
__device__ __forceinline__ unsigned long long ld_acquire_u64(const unsigned long long* p) {
    unsigned long long v;
    asm volatile("ld.acquire.gpu.global.u64 %0, [%1];" : "=l"(v) : "l"(p) : "memory");
    return v;
}
__device__ __forceinline__ void split_bf(float x, __nv_bfloat16& h, __nv_bfloat16& l) {
    h = __float2bfloat16(x);
    l = __float2bfloat16(x - __bfloat162float(h));
}
__device__ __forceinline__ uint32_t pack_bf(__nv_bfloat16 a, __nv_bfloat16 b) {
    return (uint32_t)__bfloat16_as_ushort(a) | ((uint32_t)__bfloat16_as_ushort(b) << 16);
}

// =================================================================================
// 0) zero the fps sync slots (fresh every graph replay)
// =================================================================================
__global__ void zero_slots_kernel()
{
    int i = blockIdx.x * 256 + threadIdx.x;
    if (i < NB * NS * FPSG) d_fpsKey[i] = 0ull;
}

// =================================================================================
// 0b) transpose first J0 feature columns: featT[b][n][c] = feat[b][c][n]
// =================================================================================
__global__ __launch_bounds__(256) void transT_kernel(const float* __restrict__ feat)
{
    __shared__ float tile[32][33];
    const int tx = threadIdx.x & 31, ty = threadIdx.x >> 5;   // (32, 8)
    const int n0 = blockIdx.x * 32, c0 = blockIdx.y * 32, b = blockIdx.z;
#pragma unroll
    for (int r = 0; r < 4; r++) {
        int c = c0 + ty + 8 * r;
        tile[ty + 8 * r][tx] = feat[((size_t)b * C + c) * NN + n0 + tx];
    }
    __syncthreads();
#pragma unroll
    for (int r = 0; r < 4; r++) {
        int n = n0 + ty + 8 * r;
        d_featT[((size_t)b * J0 + n) * C + c0 + tx] = tile[tx][ty + 8 * r];
    }
}

// =================================================================================
// 1) FPS, distributed: 8 blocks/batch, coords in regs, single-bar + coord-carrying
//    release/acquire slot sync. Key (distbits<<32)|(~idx): max == (maxdist, minidx).
// =================================================================================
__global__ __launch_bounds__(FPST, 1) void fps_kernel(const float* __restrict__ xyz,
                                                      float* __restrict__ out_newxyz,
                                                      float* __restrict__ out_inds)
{
    __shared__ unsigned long long sKey[FPST / 32];
    __shared__ float sCx[FPST / 32], sCy[FPST / 32], sCz[FPST / 32];

    const int b = blockIdx.x >> 3, g = blockIdx.x & 7;
    const int tid = threadIdx.x, lane = tid & 31, w = tid >> 5;
    const float* X = xyz + (size_t)b * NN * 3;
    const int n0 = g * FPSPTS + tid * 8;

    // load 8 points (24 consecutive floats) into registers
    float4 buf[6];
    const float4* src = reinterpret_cast<const float4*>(X + (size_t)n0 * 3);
#pragma unroll
    for (int i = 0; i < 6; i++) buf[i] = src[i];
    const float* bfp = reinterpret_cast<const float*>(buf);
    float px[8], py[8], pz[8], dist[8];
#pragma unroll
    for (int i = 0; i < 8; i++) {
        px[i] = bfp[3 * i]; py[i] = bfp[3 * i + 1]; pz[i] = bfp[3 * i + 2];
        dist[i] = 1e10f;
    }

    unsigned long long* keyBase = d_fpsKey + (size_t)b * NS * FPSG;
    float4* cBase = d_fpsC + (size_t)b * NS * FPSG;

    int cur = 0;
    float cx = __ldg(X), cy = __ldg(X + 1), cz = __ldg(X + 2);

    for (int it = 0; it < NS; ++it) {
        if (g == 0 && tid == 0) {
            out_inds[b * NS + it] = (float)cur;
            int o3 = (b * NS + it) * 3;
            out_newxyz[o3] = cx; out_newxyz[o3 + 1] = cy; out_newxyz[o3 + 2] = cz;
            d_newxyz[o3]   = cx; d_newxyz[o3 + 1]   = cy; d_newxyz[o3 + 2]   = cz;
        }
        // local best (value desc, index asc) + candidate coords
        float bv = -1.0f, bx = 0.f, by = 0.f, bz = 0.f; int bi = 0;
#pragma unroll
        for (int i = 0; i < 8; i++) {
            float dx = px[i] - cx, dy = py[i] - cy, dz = pz[i] - cz;
            float d  = dx * dx + dy * dy + dz * dz;
            float dm = fminf(dist[i], d);
            dist[i] = dm;
            if (dm > bv) { bv = dm; bi = n0 + i; bx = px[i]; by = py[i]; bz = pz[i]; }
        }
        if (it == NS - 1) break;                      // winner of last iter unused

        unsigned long long key = ((unsigned long long)__float_as_uint(bv) << 32)
                               | (unsigned)(0xFFFFFFFFu - (unsigned)bi);
        // warp butterfly reduce (key + coords)
#pragma unroll
        for (int off = 16; off; off >>= 1) {
            unsigned long long ok = __shfl_xor_sync(0xffffffffu, key, off);
            float ox = __shfl_xor_sync(0xffffffffu, bx, off);
            float oy = __shfl_xor_sync(0xffffffffu, by, off);
            float oz = __shfl_xor_sync(0xffffffffu, bz, off);
            if (ok > key) { key = ok; bx = ox; by = oy; bz = oz; }
        }
        if (lane == 0) { sKey[w] = key; sCx[w] = bx; sCy[w] = by; sCz[w] = bz; }
        __syncthreads();                              // sole block barrier per iter

        if (w == 0) {
            int sl = lane & 7;
            key = sKey[sl]; bx = sCx[sl]; by = sCy[sl]; bz = sCz[sl];
#pragma unroll
            for (int off = 4; off; off >>= 1) {
                unsigned long long ok = __shfl_xor_sync(0xffffffffu, key, off);
                float ox = __shfl_xor_sync(0xffffffffu, bx, off);
                float oy = __shfl_xor_sync(0xffffffffu, by, off);
                float oz = __shfl_xor_sync(0xffffffffu, bz, off);
                if (ok > key) { key = ok; bx = ox; by = oy; bz = oz; }
            }
            if (lane == 0) {
                size_t slot = (size_t)it * FPSG + g;
                cBase[slot] = make_float4(bx, by, bz, 0.f);   // payload first
                st_release_u64(&keyBase[slot], key);          // then release key
            }
        }
        // ALL warps: poll the 8 slots, reduce, adopt winner (no 2nd barrier needed:
        // poll success implies warp0 consumed smem and published)
        unsigned long long k = 0;
        float4 c4 = make_float4(0.f, 0.f, 0.f, 0.f);
        if (lane < FPSG) {
            const unsigned long long* kp = &keyBase[(size_t)it * FPSG + lane];
            do { k = ld_acquire_u64(kp); } while (k == 0ull);
            c4 = cBase[(size_t)it * FPSG + lane];             // ordered after acquire
        }
#pragma unroll
        for (int off = 16; off; off >>= 1) {
            unsigned long long ok = __shfl_xor_sync(0xffffffffu, k, off);
            float ox = __shfl_xor_sync(0xffffffffu, c4.x, off);
            float oy = __shfl_xor_sync(0xffffffffu, c4.y, off);
            float oz = __shfl_xor_sync(0xffffffffu, c4.z, off);
            if (ok > k) { k = ok; c4.x = ox; c4.y = oy; c4.z = oz; }
        }
        cur = (int)(0xFFFFFFFFu - (unsigned)k);
        cx = c4.x; cy = c4.y; cz = c4.z;
    }
}

// =================================================================================
// 2) Ball query (unchanged)
// =================================================================================
__global__ __launch_bounds__(512) void ballq_kernel(const float* __restrict__ xyz)
{
    __shared__ int slots[16][16];
    const int wl = threadIdx.x >> 5, lane = threadIdx.x & 31;
    const int w  = blockIdx.x * 16 + wl;
    const int b  = w >> 8;
    const float R2 = (float)(0.3 * 0.3);
    const int o3 = w * 3;
    const float nx = d_newxyz[o3], ny = d_newxyz[o3 + 1], nz = d_newxyz[o3 + 2];
    const float* pb = xyz + (size_t)b * NN * 3;

    int cnt = 0;
    for (int basei = 0; basei < NN && cnt < NKS; basei += 32) {
        int n = basei + lane;
        float dx = pb[3 * n] - nx, dy = pb[3 * n + 1] - ny, dz = pb[3 * n + 2] - nz;
        float d2 = dx * dx + dy * dy + dz * dz;
        bool in = d2 < R2;
        unsigned m = __ballot_sync(0xffffffffu, in);
        int pos = cnt + __popc(m & ((1u << lane) - 1u));
        if (in && pos < NKS) slots[wl][pos] = n;
        cnt += __popc(m);
    }
    __syncwarp();
    int first = slots[wl][0];
    if (lane < NKS && lane >= cnt) slots[wl][lane] = first;
    __syncwarp();
    if (lane < NKS) d_idx[w * NKS + lane] = slots[wl][lane];
}

// =================================================================================
// 3) Weight prep (unchanged)
// =================================================================================
__global__ __launch_bounds__(256) void wprep_kernel(const float* __restrict__ W, int Kdim,
                                                    int perm0, unsigned char* __restrict__ whi,
                                                    unsigned char* __restrict__ wlo)
{
    int id = blockIdx.x * 256 + threadIdx.x;
    if (id >= C * 40) return;
    int o = id / 40, u = id % 40;
    uint32_t h[4], l[4];
#pragma unroll
    for (int e = 0; e < 4; e++) {
        __nv_bfloat16 hh[2], ll[2];
#pragma unroll
        for (int q = 0; q < 2; q++) {
            int c = u * 8 + e * 2 + q;
            int src;
            if (perm0) src = (c < 288) ? c + 3 : ((c < 291) ? c - 288 : -1);
            else       src = (c < Kdim) ? c : -1;
            float v = (src >= 0) ? W[o * Kdim + src] : 0.0f;
            split_bf(v, hh[q], ll[q]);
        }
        h[e] = pack_bf(hh[0], hh[1]);
        l[e] = pack_bf(ll[0], ll[1]);
    }
    size_t off = (size_t)(u / 8) * B_CHUNK_B + SWZ((uint32_t)(o * 128 + (u % 8) * 16));
    *reinterpret_cast<uint4*>(whi + off) = make_uint4(h[0], h[1], h[2], h[3]);
    *reinterpret_cast<uint4*>(wlo + off) = make_uint4(l[0], l[1], l[2], l[3]);
}

// =================================================================================
// 4) Gather: layer-0 A tiles; coalesced fast path via d_featT for j < J0
// =================================================================================
__global__ __launch_bounds__(128) void gather_kernel(const float* __restrict__ xyz,
                                                     const float* __restrict__ feat)
{
    __shared__ __align__(16) __nv_bfloat16 sH[4][320];
    __shared__ __align__(16) __nv_bfloat16 sL[4][320];
    const int wid = threadIdx.x >> 5, lane = threadIdx.x & 31;
    const int p = blockIdx.x * 4 + wid;
    const int b = p >> 12, s = (p >> 4) & 255;
    const int j = d_idx[p];

    float f[9];
    if (j < J0) {
        const float* fb = d_featT + ((size_t)b * J0 + j) * C;
#pragma unroll
        for (int r = 0; r < 9; r++) f[r] = fb[lane + 32 * r];
    } else {
        const float* fb = feat + (size_t)b * C * NN + j;
#pragma unroll
        for (int r = 0; r < 9; r++) f[r] = fb[(size_t)(lane + 32 * r) * NN];
    }
#pragma unroll
    for (int r = 0; r < 9; r++) {
        __nv_bfloat16 h, l; split_bf(f[r], h, l);
        sH[wid][lane + 32 * r] = h; sL[wid][lane + 32 * r] = l;
    }
    if (lane < 3) {
        float gv = xyz[((size_t)b * NN + j) * 3 + lane];
        float cv = d_newxyz[(b * NS + s) * 3 + lane];
        float rel = (gv - cv) / 0.3f;
        __nv_bfloat16 h, l; split_bf(rel, h, l);
        sH[wid][288 + lane] = h; sL[wid][288 + lane] = l;
    } else {
        sH[wid][288 + lane] = __ushort_as_bfloat16(0);
        sL[wid][288 + lane] = __ushort_as_bfloat16(0);
    }
    __syncwarp();

    const size_t tbase = (size_t)(p >> 7) * A_TILE_B;
    const int row = p & 127;
    const char* srcH = reinterpret_cast<const char*>(&sH[wid][0]);
    const char* srcL = reinterpret_cast<const char*>(&sL[wid][0]);
#pragma unroll
    for (int u = lane; u < 40; u += 32) {
        size_t off = tbase + (size_t)(u / 8) * A_CHUNK_B + SWZ((uint32_t)(row * 128 + (u % 8) * 16));
        *reinterpret_cast<uint4*>(d_Xhi + off) = *reinterpret_cast<const uint4*>(srcH + u * 16);
        *reinterpret_cast<uint4*>(d_Xlo + off) = *reinterpret_cast<const uint4*>(srcL + u * 16);
    }
}

// =================================================================================
// 5) GEMM + BN + ReLU via mma.sync bf16 hi/lo split (unchanged from R5 — passing)
// =================================================================================
template <bool LAST>
__global__ __launch_bounds__(256, 1) void mma_gemm(const unsigned char* __restrict__ Ahi,
                                                   const unsigned char* __restrict__ Alo,
                                                   const unsigned char* __restrict__ Bhi,
                                                   const unsigned char* __restrict__ Blo,
                                                   unsigned char* __restrict__ OutHi,
                                                   unsigned char* __restrict__ OutLo,
                                                   float* __restrict__ OutFeat,
                                                   const float* __restrict__ gg,
                                                   const float* __restrict__ bb,
                                                   const float* __restrict__ mm,
                                                   const float* __restrict__ vv)
{
    extern __shared__ char dynsm[];
    __shared__ float sc[144], sh[144];

    const int t = threadIdx.x, lane = t & 31, w = t >> 5;
    const int wr = w & 3, wc = w >> 2;
    const int half = blockIdx.y;

    char* basep = (char*)(((uintptr_t)dynsm + 1023) & ~(uintptr_t)1023);
    const uint32_t tb = smem_u32(basep);

    if (t < 144) {
        int o = half * 144 + t;
        float s = gg[o] * rsqrtf(vv[o] + 1e-5f);
        sc[t] = s; sh[t] = bb[o] - mm[o] * s;
    }

    const unsigned char* Ath = Ahi + (size_t)blockIdx.x * A_TILE_B;
    const unsigned char* Atl = Alo + (size_t)blockIdx.x * A_TILE_B;
    const unsigned char* Bh  = Bhi + (size_t)half * BH_B;
    const unsigned char* Bl  = Blo + (size_t)half * BH_B;

    auto load_chunk = [&](int c) {
        uint32_t s = tb + (uint32_t)(c & 1) * STG;
        const unsigned char* ah = Ath + (size_t)c * A_CHUNK_B;
        const unsigned char* al = Atl + (size_t)c * A_CHUNK_B;
#pragma unroll
        for (int i = 0; i < 4; i++) {
            int e = t + 256 * i;
            cp16(s + SA_H + e * 16, ah + (size_t)e * 16);
            cp16(s + SA_L + e * 16, al + (size_t)e * 16);
        }
        const unsigned char* bh = Bh + (size_t)c * B_CHUNK_B;
        const unsigned char* bl = Bl + (size_t)c * B_CHUNK_B;
#pragma unroll
        for (int i = 0; i < 5; i++) {
            int e = t + 256 * i;
            if (e < 1152) {
                cp16(s + SB_H + e * 16, bh + (size_t)e * 16);
                cp16(s + SB_L + e * 16, bl + (size_t)e * 16);
            }
        }
    };

    float acc[2][9][4];
#pragma unroll
    for (int i = 0; i < 2; i++)
#pragma unroll
        for (int j = 0; j < 9; j++)
#pragma unroll
            for (int q = 0; q < 4; q++) acc[i][j][q] = 0.0f;

    load_chunk(0); CP_COMMIT();

    for (int c = 0; c < NCHUNK; ++c) {
        if (c + 1 < NCHUNK) { load_chunk(c + 1); CP_COMMIT(); cp_wait<1>(); }
        else                { cp_wait<0>(); }
        __syncthreads();

        const uint32_t s = tb + (uint32_t)(c & 1) * STG;
#pragma unroll
        for (int ks = 0; ks < 4; ++ks) {
            const uint32_t kb = ks * 32;
            uint32_t ahf[2][4], alf[2][4];
            {
                const int lr = lane & 15, lh = lane >> 4;
#pragma unroll
                for (int i = 0; i < 2; i++) {
                    uint32_t off = SWZ((uint32_t)((wr * 32 + i * 16 + lr) * 128 + kb + lh * 16));
                    ldmx4(ahf[i], s + SA_H + off);
                    ldmx4(alf[i], s + SA_L + off);
                }
            }
            uint32_t bhf[9][2], blf[9][2];
            {
                const int rb = (lane & 7) + ((lane >> 4) << 3);
                const int kseg = ((lane >> 3) & 1) * 16;
#pragma unroll
                for (int jj = 0; jj < 4; jj++) {
                    uint32_t off = SWZ((uint32_t)((wc * 72 + jj * 16 + rb) * 128 + kb + kseg));
                    uint32_t tmp[4];
                    ldmx4(tmp, s + SB_H + off);
                    bhf[2 * jj][0] = tmp[0]; bhf[2 * jj][1] = tmp[1];
                    bhf[2 * jj + 1][0] = tmp[2]; bhf[2 * jj + 1][1] = tmp[3];
                    ldmx4(tmp, s + SB_L + off);
                    blf[2 * jj][0] = tmp[0]; blf[2 * jj][1] = tmp[1];
                    blf[2 * jj + 1][0] = tmp[2]; blf[2 * jj + 1][1] = tmp[3];
                }
                uint32_t off8 = SWZ((uint32_t)((wc * 72 + 64 + (lane & 7)) * 128 + kb + kseg));
                ldmx2(bhf[8], s + SB_H + off8);
                ldmx2(blf[8], s + SB_L + off8);
            }
#pragma unroll
            for (int i = 0; i < 2; i++)
#pragma unroll
                for (int j = 0; j < 9; j++) {
                    mma16816(acc[i][j], ahf[i], bhf[j]);
                    mma16816(acc[i][j], ahf[i], blf[j]);
                    mma16816(acc[i][j], alf[i], bhf[j]);
                }
        }
        __syncthreads();
    }

    // ---------------- epilogue ----------------
    if (!LAST) {
        unsigned char* Oth = OutHi + (size_t)blockIdx.x * A_TILE_B;
        unsigned char* Otl = OutLo + (size_t)blockIdx.x * A_TILE_B;
#pragma unroll
        for (int i = 0; i < 2; i++) {
            const int r1 = wr * 32 + i * 16 + (lane >> 2);
#pragma unroll
            for (int j = 0; j < 9; j++) {
                const int ol = wc * 72 + j * 8 + 2 * (lane & 3);
                const int og = half * 144 + ol;
                const int chunk = og >> 6;
                const int c2 = (og & 63) * 2;
                const float s0 = sc[ol], h0 = sh[ol], s1 = sc[ol + 1], h1 = sh[ol + 1];
#pragma unroll
                for (int rh = 0; rh < 2; rh++) {
                    const int row = r1 + rh * 8;
                    float x0 = fmaxf(acc[i][j][rh * 2 + 0] * s0 + h0, 0.0f);
                    float x1 = fmaxf(acc[i][j][rh * 2 + 1] * s1 + h1, 0.0f);
                    __nv_bfloat16 hh0, ll0, hh1, ll1;
                    split_bf(x0, hh0, ll0); split_bf(x1, hh1, ll1);
                    uint32_t off = (uint32_t)chunk * A_CHUNK_B + SWZ((uint32_t)(row * 128 + c2));
                    *reinterpret_cast<uint32_t*>(Oth + off) = pack_bf(hh0, hh1);
                    *reinterpret_cast<uint32_t*>(Otl + off) = pack_bf(ll0, ll1);
                }
            }
        }
        if (half == 0) {
            const int row = t & 127;
#pragma unroll
            for (int m = (t >> 7); m < 4; m += 2) {
                uint32_t off = 4u * A_CHUNK_B + SWZ((uint32_t)(row * 128 + 64 + m * 16));
                *reinterpret_cast<uint4*>(Oth + off) = make_uint4(0, 0, 0, 0);
                *reinterpret_cast<uint4*>(Otl + off) = make_uint4(0, 0, 0, 0);
            }
        }
    } else {
#pragma unroll
        for (int i = 0; i < 2; i++) {
            const int p0 = blockIdx.x * 128 + wr * 32 + i * 16;
            const int gidx = p0 >> 4;
            const int b = gidx >> 8, sIdx = gidx & 255;
#pragma unroll
            for (int j = 0; j < 9; j++) {
                const int ol = wc * 72 + j * 8 + 2 * (lane & 3);
                const int og = half * 144 + ol;
                const float s0 = sc[ol], h0 = sh[ol], s1 = sc[ol + 1], h1 = sh[ol + 1];
                float m0 = fmaxf(fmaxf(acc[i][j][0] * s0 + h0, 0.0f),
                                 fmaxf(acc[i][j][2] * s0 + h0, 0.0f));
                float m1 = fmaxf(fmaxf(acc[i][j][1] * s1 + h1, 0.0f),
                                 fmaxf(acc[i][j][3] * s1 + h1, 0.0f));
#pragma unroll
                for (int msk = 4; msk <= 16; msk <<= 1) {
                    m0 = fmaxf(m0, __shfl_xor_sync(0xffffffffu, m0, msk));
                    m1 = fmaxf(m1, __shfl_xor_sync(0xffffffffu, m1, msk));
                }
                if (lane < 4) {
                    OutFeat[((size_t)b * C + og) * NS + sIdx]     = m0;
                    OutFeat[((size_t)b * C + og + 1) * NS + sIdx] = m1;
                }
            }
        }
    }
}

// =================================================================================
extern "C" void kernel_launch(void* const* d_in, const int* in_sizes, int n_in,
                              void* d_out, int out_size)
{
    const float* xyz  = (const float*)d_in[0];
    const float* feat = (const float*)d_in[1];
    const float* W[3] = { (const float*)d_in[2], (const float*)d_in[7], (const float*)d_in[12] };
    const float* G[3] = { (const float*)d_in[3], (const float*)d_in[8], (const float*)d_in[13] };
    const float* Bp[3]= { (const float*)d_in[4], (const float*)d_in[9], (const float*)d_in[14] };
    const float* M[3] = { (const float*)d_in[5], (const float*)d_in[10], (const float*)d_in[15] };
    const float* V[3] = { (const float*)d_in[6], (const float*)d_in[11], (const float*)d_in[16] };

    float* out        = (float*)d_out;
    float* out_newxyz = out;
    float* out_feat   = out + NB * NS * 3;
    float* out_inds   = out + NB * NS * 3 + (size_t)NB * C * NS;

    unsigned char *Xhi, *Xlo, *Yhi, *Ylo, *Whi, *Wlo;
    cudaGetSymbolAddress((void**)&Xhi, d_Xhi);
    cudaGetSymbolAddress((void**)&Xlo, d_Xlo);
    cudaGetSymbolAddress((void**)&Yhi, d_Yhi);
    cudaGetSymbolAddress((void**)&Ylo, d_Ylo);
    cudaGetSymbolAddress((void**)&Whi, d_Whi);
    cudaGetSymbolAddress((void**)&Wlo, d_Wlo);

    cudaFuncSetAttribute(mma_gemm<false>, cudaFuncAttributeMaxDynamicSharedMemorySize, DYN_SMEM);
    cudaFuncSetAttribute(mma_gemm<true>,  cudaFuncAttributeMaxDynamicSharedMemorySize, DYN_SMEM);

    const int wgrid = (C * 40 + 255) / 256;
    // launch order arranged so ncu (-s 5 -c 1) profiles fps_kernel (6th launch)
    wprep_kernel<<<wgrid, 256>>>(W[0], 291, 1, Whi, Wlo);
    wprep_kernel<<<wgrid, 256>>>(W[1], 288, 0, Whi + W_LAYER_B, Wlo + W_LAYER_B);
    wprep_kernel<<<wgrid, 256>>>(W[2], 288, 0, Whi + 2 * W_LAYER_B, Wlo + 2 * W_LAYER_B);
    zero_slots_kernel<<<(NB * NS * FPSG + 255) / 256, 256>>>();
    transT_kernel<<<dim3(J0 / 32, C / 32, NB), 256>>>(feat);

    fps_kernel<<<NB * FPSG, FPST>>>(xyz, out_newxyz, out_inds);
    ballq_kernel<<<NB * NS / 16, 512>>>(xyz);
    gather_kernel<<<PTOT / 4, 128>>>(xyz, feat);

    mma_gemm<false><<<dim3(NTILES, 2), 256, DYN_SMEM>>>(Xhi, Xlo, Whi, Wlo,
                                                        Yhi, Ylo, nullptr,
                                                        G[0], Bp[0], M[0], V[0]);
    mma_gemm<false><<<dim3(NTILES, 2), 256, DYN_SMEM>>>(Yhi, Ylo, Whi + W_LAYER_B, Wlo + W_LAYER_B,
                                                        Xhi, Xlo, nullptr,
                                                        G[1], Bp[1], M[1], V[1]);
    mma_gemm<true><<<dim3(NTILES, 2), 256, DYN_SMEM>>>(Xhi, Xlo, Whi + 2 * W_LAYER_B, Wlo + 2 * W_LAYER_B,
                                                       nullptr, nullptr, out_feat,
                                                       G[2], Bp[2], M[2], V[2]);
}